// round 8
// baseline (speedup 1.0000x reference)
#include <cuda_runtime.h>
#include <cuda_fp16.h>
#include <math.h>
#include <stdint.h>

// Problem constants
#define B_    4
#define L_    2048
#define E_    1024
#define H_    16
#define DK_   64
#define MTOK  (B_ * L_)          // 8192
#define QKV_N (3 * H_ * DK_)     // 3072
#define HD_   (H_ * DK_)         // 1024
#define KDIM  1024

// ---------------------------------------------------------------------------
// Scratch (__device__ globals; allocation-free rule)
// ---------------------------------------------------------------------------
__device__ __half g_Xh[(size_t)MTOK * E_];
__device__ __half g_Xl[(size_t)MTOK * E_];
__device__ __half g_Wqh[(size_t)QKV_N * E_];     // transposed [N][K], hi only
__device__ __half g_Wfh[(size_t)E_ * HD_];       // transposed [N][K], hi only
__device__ __half g_qkvh[(size_t)MTOK * QKV_N];  // [token][3*H*DK]
__device__ __half g_qkvl[(size_t)MTOK * QKV_N];
__device__ __half g_Ath[(size_t)MTOK * HD_];     // attention out hi/lo
__device__ __half g_Atl[(size_t)MTOK * HD_];

// ---------------------------------------------------------------------------
// PTX helpers (sm_80+ only: ldmatrix, mma.sync f16, cp.async)
// ---------------------------------------------------------------------------
__device__ __forceinline__ uint32_t smem_u32(const void* p) {
    uint32_t a;
    asm("{ .reg .u64 t; cvta.to.shared.u64 t, %1; cvt.u32.u64 %0, t; }"
        : "=r"(a) : "l"(p));
    return a;
}
__device__ __forceinline__ void ldsm4(uint32_t* r, uint32_t addr) {
    asm volatile("ldmatrix.sync.aligned.m8n8.x4.shared.b16 {%0,%1,%2,%3}, [%4];"
        : "=r"(r[0]), "=r"(r[1]), "=r"(r[2]), "=r"(r[3]) : "r"(addr));
}
__device__ __forceinline__ void ldsm4t(uint32_t* r, uint32_t addr) {
    asm volatile("ldmatrix.sync.aligned.m8n8.x4.trans.shared.b16 {%0,%1,%2,%3}, [%4];"
        : "=r"(r[0]), "=r"(r[1]), "=r"(r[2]), "=r"(r[3]) : "r"(addr));
}
__device__ __forceinline__ void mma_f16(float* c, const uint32_t* a, const uint32_t* b) {
    asm volatile(
        "mma.sync.aligned.m16n8k16.row.col.f32.f16.f16.f32 "
        "{%0,%1,%2,%3},{%4,%5,%6,%7},{%8,%9},{%0,%1,%2,%3};"
        : "+f"(c[0]), "+f"(c[1]), "+f"(c[2]), "+f"(c[3])
        : "r"(a[0]), "r"(a[1]), "r"(a[2]), "r"(a[3]), "r"(b[0]), "r"(b[1]));
}
__device__ __forceinline__ void cp16(uint32_t dst, const void* src) {
    asm volatile("cp.async.cg.shared.global [%0], [%1], 16;" :: "r"(dst), "l"(src));
}
#define CP_COMMIT() asm volatile("cp.async.commit_group;" ::: "memory")
#define CP_WAIT1()  asm volatile("cp.async.wait_group 1;" ::: "memory")
#define CP_WAIT0()  asm volatile("cp.async.wait_group 0;" ::: "memory")

// fp16 hi/lo pack: hi = rn(x), lo = rn(x - hi); hi+lo carries ~22 mantissa bits
__device__ __forceinline__ uint32_t pack_hi16(float x, float y, uint32_t& lo) {
    __half2 h, l;
    h.x = __float2half_rn(x);
    h.y = __float2half_rn(y);
    l.x = __float2half_rn(x - __half2float(h.x));
    l.y = __float2half_rn(y - __half2float(h.y));
    lo = *(uint32_t*)&l;
    return *(uint32_t*)&h;
}

// ---------------------------------------------------------------------------
// Conversion kernels
// ---------------------------------------------------------------------------
__global__ void convert_split16(const float4* __restrict__ in,
                                uint32_t* __restrict__ hi2, uint32_t* __restrict__ lo2,
                                int n4)
{
    int i = blockIdx.x * blockDim.x + threadIdx.x;
    if (i >= n4) return;
    float4 v = in[i];
    uint32_t l0, l1;
    uint32_t h0 = pack_hi16(v.x, v.y, l0);
    uint32_t h1 = pack_hi16(v.z, v.w, l1);
    hi2[2 * i] = h0; hi2[2 * i + 1] = h1;
    lo2[2 * i] = l0; lo2[2 * i + 1] = l1;
}

// W[K][N] row-major -> T[N][K] fp16 hi (transpose)
__global__ __launch_bounds__(256) void wt_convert16(
    const float* __restrict__ W, __half* __restrict__ Th, int K, int N)
{
    __shared__ float tile[32][33];
    const int n0 = blockIdx.x * 32, k0 = blockIdx.y * 32;
    const int tx = threadIdx.x & 31, ty = threadIdx.x >> 5;
    #pragma unroll
    for (int r = 0; r < 32; r += 8)
        tile[ty + r][tx] = W[(size_t)(k0 + ty + r) * N + n0 + tx];
    __syncthreads();
    #pragma unroll
    for (int r = 0; r < 32; r += 8) {
        const int n = n0 + ty + r, k = k0 + tx;
        Th[(size_t)n * K + k] = __float2half_rn(tile[tx][ty + r]);
    }
}

// ---------------------------------------------------------------------------
// fp16x2 GEMM: C[M,N] = (Ah+Al)[M,K] @ Bh[N,K]^T + bias.
// 128x128 tile, BK=32, 256 thr = 8 warps (2m x 4n), warp 64x32.
// 3-stage cp.async pipeline, ONE __syncthreads per k-iter.
// Stage = AH(8K) AL(8K) BH(8K) = 24KB; 3 stages = 72KB.
// 8x8-b16 tiles contiguous (128B) for conflict-free LDSM.
// ---------------------------------------------------------------------------
#define STG 24576
#define GEMM_SMEM_BYTES (3 * STG)   // 73728
#define NCHUNK (KDIM / 32)          // 32

__global__ __launch_bounds__(256) void gemm_f16x2(
    const __half* __restrict__ Agh, const __half* __restrict__ Agl,
    const __half* __restrict__ Bgh,
    const float* __restrict__ bias, float* __restrict__ Cf,
    __half* __restrict__ Cbh, __half* __restrict__ Cbl, int N)
{
    extern __shared__ __align__(1024) char smem[];
    const uint32_t sbase = smem_u32(smem);
    const int tid = threadIdx.x, lane = tid & 31, warp = tid >> 5;
    const int wm = warp & 1, wn = warp >> 1;
    const int brow = blockIdx.y * 128, bcol = blockIdx.x * 128;

    float acc[4][4][4] = {};

    auto stage = [&](int kt, int buf) {
        const int k0 = kt * 32;
        const uint32_t b0 = sbase + buf * STG;
        #pragma unroll
        for (int p = 0; p < 2; ++p) {
            const int idx = tid + p * 256;
            const int r = idx & 127, kc = idx >> 7;
            const uint32_t soff = (uint32_t)(((r >> 3) * 4 + kc) * 128 + (r & 7) * 16);
            const size_t ga = (size_t)(brow + r) * KDIM + k0 + kc * 8;
            const size_t gb = (size_t)(bcol + r) * KDIM + k0 + kc * 8;
            cp16(b0 + soff,         Agh + ga);
            cp16(b0 + 8192 + soff,  Agl + ga);
            cp16(b0 + 16384 + soff, Bgh + gb);
        }
    };

    auto compute = [&](int buf) {
        const uint32_t b0 = sbase + buf * STG;
        const int g = lane >> 3, row = lane & 7;
        #pragma unroll
        for (int s = 0; s < 2; ++s) {
            uint32_t aH[4][4], aL[4][4], bH[2][4];
            #pragma unroll
            for (int mi = 0; mi < 4; ++mi) {
                const int mt0 = wm * 8 + mi * 2;
                const uint32_t tile = (uint32_t)((mt0 + (g & 1)) * 4 + 2 * s + (g >> 1));
                const uint32_t addr = b0 + tile * 128 + row * 16;
                ldsm4(aH[mi], addr);
                ldsm4(aL[mi], addr + 8192);
            }
            #pragma unroll
            for (int hf = 0; hf < 2; ++hf) {
                const int ng = wn * 4 + hf * 2;
                const uint32_t tile = (uint32_t)((ng + (g >> 1)) * 4 + 2 * s + (g & 1));
                ldsm4(bH[hf], b0 + 16384 + tile * 128 + row * 16);
            }
            #pragma unroll
            for (int mi = 0; mi < 4; ++mi)
                #pragma unroll
                for (int nj = 0; nj < 4; ++nj) {
                    const uint32_t* bh = &bH[nj >> 1][(nj & 1) * 2];
                    mma_f16(acc[mi][nj], aH[mi], bh);
                    mma_f16(acc[mi][nj], aL[mi], bh);
                }
        }
    };

    stage(0, 0); CP_COMMIT();
    stage(1, 1); CP_COMMIT();
    for (int kt = 0; kt < NCHUNK; ++kt) {
        if (kt + 1 < NCHUNK) { CP_WAIT1(); } else { CP_WAIT0(); }
        __syncthreads();   // group kt visible to all; prev compute on (kt+2)%3 done
        if (kt + 2 < NCHUNK) { stage(kt + 2, (kt + 2) % 3); CP_COMMIT(); }
        compute(kt % 3);
    }

    const int r4 = lane >> 2, c2 = (lane & 3) * 2;
    #pragma unroll
    for (int mi = 0; mi < 4; ++mi) {
        const int row = brow + wm * 64 + mi * 16 + r4;
        #pragma unroll
        for (int nj = 0; nj < 4; ++nj) {
            const int col = bcol + wn * 32 + nj * 8 + c2;
            const float b0 = __ldg(&bias[col]), b1 = __ldg(&bias[col + 1]);
            const float x0 = acc[mi][nj][0] + b0, y0 = acc[mi][nj][1] + b1;
            const float x1 = acc[mi][nj][2] + b0, y1 = acc[mi][nj][3] + b1;
            if (Cf) {
                *(float2*)(Cf + (size_t)row * N + col) = make_float2(x0, y0);
                *(float2*)(Cf + (size_t)(row + 8) * N + col) = make_float2(x1, y1);
            } else {
                uint32_t l0, l1;
                const uint32_t h0 = pack_hi16(x0, y0, l0);
                const uint32_t h1 = pack_hi16(x1, y1, l1);
                *(uint32_t*)(Cbh + (size_t)row * N + col) = h0;
                *(uint32_t*)(Cbl + (size_t)row * N + col) = l0;
                *(uint32_t*)(Cbh + (size_t)(row + 8) * N + col) = h1;
                *(uint32_t*)(Cbl + (size_t)(row + 8) * N + col) = l1;
            }
        }
    }
}

// ---------------------------------------------------------------------------
// Flash attention, fp16x2 mma. Grid (L/128, H, B), 256 thr = 8 warps.
// Warp w owns q rows [16w, 16w+16). Key chunks of 64.
// A-side split: Q hi/lo, P hi/lo. B-side single: K hi, V hi.
// SMEM (80KB): QH 0(16K) QL 16K | KH 32K(8K) | VH 40K(8K)
//              PH 48K(16K = 8 warps x 2K) PL 64K
// ---------------------------------------------------------------------------
#define AS_QH 0
#define AS_QL 16384
#define AS_KH 32768
#define AS_VH 40960
#define AS_PH 49152
#define AS_PL 65536
#define ATTN_SMEM_BYTES 81920

__global__ __launch_bounds__(256) void attn_f16x2(
    const __half* __restrict__ qh, const __half* __restrict__ ql,
    __half* __restrict__ oh, __half* __restrict__ ol)
{
    extern __shared__ __align__(1024) char smem[];
    const uint32_t sbase = smem_u32(smem);
    const int b = blockIdx.z, h = blockIdx.y, q0 = blockIdx.x * 128;
    const int tid = threadIdx.x, lane = tid & 31, warp = tid >> 5;
    const int g = lane >> 3, lrow = lane & 7;
    const size_t hbase = (size_t)h * (3 * DK_);

    // ---- stage Q (128 x 64 hi/lo) ----
    for (int idx = tid; idx < 1024; idx += 256) {
        const int r = idx >> 3, c = idx & 7;
        const uint32_t soff = (uint32_t)(((r >> 3) * 8 + c) * 128 + (r & 7) * 16);
        const size_t ga = ((size_t)b * L_ + q0 + r) * QKV_N + hbase + c * 8;
        cp16(sbase + AS_QH + soff, qh + ga);
        cp16(sbase + AS_QL + soff, ql + ga);
    }
    CP_COMMIT();

    float oacc[8][4] = {};
    float m0 = -INFINITY, m1 = -INFINITY, l0 = 0.f, l1 = 0.f;
    const float scale = 0.125f;

    for (int kc = 0; kc < L_; kc += 64) {
        __syncthreads();   // all warps done reading prev K/V
        // ---- stage K,V chunk (64 x 64, hi only) ----
        for (int idx = tid; idx < 512; idx += 256) {
            const int r = idx >> 3, c = idx & 7;
            const uint32_t soff = (uint32_t)(((r >> 3) * 8 + c) * 128 + (r & 7) * 16);
            const size_t ga = ((size_t)b * L_ + kc + r) * QKV_N + hbase + c * 8;
            cp16(sbase + AS_KH + soff, qh + ga + DK_);
            cp16(sbase + AS_VH + soff, qh + ga + 2 * DK_);
        }
        CP_COMMIT();
        CP_WAIT0();
        __syncthreads();

        // ---- S = (Qh+Ql) K^T : 16(q) x 64(key), k = 64(d) ----
        float sacc[8][4] = {};
        #pragma unroll
        for (int s = 0; s < 4; ++s) {
            uint32_t aH[4], aL[4];
            {
                const int mt0 = warp * 2;
                const uint32_t tile = (uint32_t)((mt0 + (g & 1)) * 8 + 2 * s + (g >> 1));
                const uint32_t addr = sbase + AS_QH + tile * 128 + lrow * 16;
                ldsm4(aH, addr);
                ldsm4(aL, addr + (AS_QL - AS_QH));
            }
            #pragma unroll
            for (int hf = 0; hf < 4; ++hf) {
                uint32_t bH[4];
                const int ng = hf * 2;
                const uint32_t tile = (uint32_t)((ng + (g >> 1)) * 8 + 2 * s + (g & 1));
                ldsm4(bH, sbase + AS_KH + tile * 128 + lrow * 16);
                #pragma unroll
                for (int q = 0; q < 2; ++q) {
                    float* c = sacc[ng + q];
                    mma_f16(c, aH, &bH[q * 2]);
                    mma_f16(c, aL, &bH[q * 2]);
                }
            }
        }

        // ---- online softmax (row0 = regs 0,1 ; row1 = regs 2,3) ----
        {
            float mloc = -INFINITY;
            #pragma unroll
            for (int nj = 0; nj < 8; ++nj) {
                sacc[nj][0] *= scale; sacc[nj][1] *= scale;
                mloc = fmaxf(mloc, fmaxf(sacc[nj][0], sacc[nj][1]));
            }
            mloc = fmaxf(mloc, __shfl_xor_sync(0xffffffffu, mloc, 1));
            mloc = fmaxf(mloc, __shfl_xor_sync(0xffffffffu, mloc, 2));
            const float mnew = fmaxf(m0, mloc);
            const float corr = __expf(m0 - mnew);
            m0 = mnew;
            float lsum = 0.f;
            #pragma unroll
            for (int nj = 0; nj < 8; ++nj) {
                const float p0 = __expf(sacc[nj][0] - mnew);
                const float p1 = __expf(sacc[nj][1] - mnew);
                sacc[nj][0] = p0; sacc[nj][1] = p1;
                lsum += p0 + p1;
            }
            lsum += __shfl_xor_sync(0xffffffffu, lsum, 1);
            lsum += __shfl_xor_sync(0xffffffffu, lsum, 2);
            l0 = l0 * corr + lsum;
            #pragma unroll
            for (int nj = 0; nj < 8; ++nj) { oacc[nj][0] *= corr; oacc[nj][1] *= corr; }
        }
        {
            float mloc = -INFINITY;
            #pragma unroll
            for (int nj = 0; nj < 8; ++nj) {
                sacc[nj][2] *= scale; sacc[nj][3] *= scale;
                mloc = fmaxf(mloc, fmaxf(sacc[nj][2], sacc[nj][3]));
            }
            mloc = fmaxf(mloc, __shfl_xor_sync(0xffffffffu, mloc, 1));
            mloc = fmaxf(mloc, __shfl_xor_sync(0xffffffffu, mloc, 2));
            const float mnew = fmaxf(m1, mloc);
            const float corr = __expf(m1 - mnew);
            m1 = mnew;
            float lsum = 0.f;
            #pragma unroll
            for (int nj = 0; nj < 8; ++nj) {
                const float p0 = __expf(sacc[nj][2] - mnew);
                const float p1 = __expf(sacc[nj][3] - mnew);
                sacc[nj][2] = p0; sacc[nj][3] = p1;
                lsum += p0 + p1;
            }
            lsum += __shfl_xor_sync(0xffffffffu, lsum, 1);
            lsum += __shfl_xor_sync(0xffffffffu, lsum, 2);
            l1 = l1 * corr + lsum;
            #pragma unroll
            for (int nj = 0; nj < 8; ++nj) { oacc[nj][2] *= corr; oacc[nj][3] *= corr; }
        }

        // ---- store P (16 x 64) hi/lo into per-warp tile region ----
        {
            const int r4 = lane >> 2, cb = 4 * (lane & 3);
            #pragma unroll
            for (int nj = 0; nj < 8; ++nj) {
                uint32_t plo;
                const uint32_t ph0 = pack_hi16(sacc[nj][0], sacc[nj][1], plo);
                const uint32_t off0 = (uint32_t)((0 * 8 + nj) * 128 + r4 * 16 + cb);
                *(uint32_t*)(smem + AS_PH + warp * 2048 + off0) = ph0;
                *(uint32_t*)(smem + AS_PL + warp * 2048 + off0) = plo;
                const uint32_t ph1 = pack_hi16(sacc[nj][2], sacc[nj][3], plo);
                const uint32_t off1 = (uint32_t)((1 * 8 + nj) * 128 + r4 * 16 + cb);
                *(uint32_t*)(smem + AS_PH + warp * 2048 + off1) = ph1;
                *(uint32_t*)(smem + AS_PL + warp * 2048 + off1) = plo;
            }
        }
        __syncwarp();

        // ---- O += (Ph+Pl) V : 16(q) x 64(d), k = 64(key) ----
        #pragma unroll
        for (int s = 0; s < 4; ++s) {
            uint32_t aH[4], aL[4];
            {
                const uint32_t tile = (uint32_t)((g & 1) * 8 + 2 * s + (g >> 1));
                const uint32_t addr = sbase + AS_PH + warp * 2048 + tile * 128 + lrow * 16;
                ldsm4(aH, addr);
                ldsm4(aL, addr + (AS_PL - AS_PH));
            }
            #pragma unroll
            for (int hf = 0; hf < 4; ++hf) {
                uint32_t bH[4];
                const int dt = hf * 2;
                const uint32_t tile = (uint32_t)((2 * s + (g & 1)) * 8 + dt + (g >> 1));
                ldsm4t(bH, sbase + AS_VH + tile * 128 + lrow * 16);
                #pragma unroll
                for (int q = 0; q < 2; ++q) {
                    float* c = oacc[dt + q];
                    mma_f16(c, aH, &bH[q * 2]);
                    mma_f16(c, aL, &bH[q * 2]);
                }
            }
        }
    }

    // ---- epilogue: normalize, split, write fp16 hi/lo [token][HD] ----
    const float inv0 = 1.f / l0, inv1 = 1.f / l1;
    const int r4 = lane >> 2, c2 = 2 * (lane & 3);
    const size_t row0 = (size_t)b * L_ + q0 + warp * 16 + r4;
    #pragma unroll
    for (int nj = 0; nj < 8; ++nj) {
        const int col = h * DK_ + nj * 8 + c2;
        uint32_t lo;
        const uint32_t h0 = pack_hi16(oacc[nj][0] * inv0, oacc[nj][1] * inv0, lo);
        *(uint32_t*)(oh + row0 * HD_ + col) = h0;
        *(uint32_t*)(ol + row0 * HD_ + col) = lo;
        const uint32_t h1 = pack_hi16(oacc[nj][2] * inv1, oacc[nj][3] * inv1, lo);
        *(uint32_t*)(oh + (row0 + 8) * HD_ + col) = h1;
        *(uint32_t*)(ol + (row0 + 8) * HD_ + col) = lo;
    }
}

// ---------------------------------------------------------------------------
// Launch
// ---------------------------------------------------------------------------
extern "C" void kernel_launch(void* const* d_in, const int* in_sizes, int n_in,
                              void* d_out, int out_size)
{
    const float* X    = (const float*)d_in[0];
    const float* Wqkv = (const float*)d_in[1];
    const float* bqkv = (const float*)d_in[2];
    const float* Wfc  = (const float*)d_in[3];
    const float* bfc  = (const float*)d_in[4];
    float* out = (float*)d_out;

    __half *Xh, *Xl, *Wqh, *Wfh, *qkvh, *qkvl, *Ath, *Atl;
    cudaGetSymbolAddress((void**)&Xh, g_Xh);
    cudaGetSymbolAddress((void**)&Xl, g_Xl);
    cudaGetSymbolAddress((void**)&Wqh, g_Wqh);
    cudaGetSymbolAddress((void**)&Wfh, g_Wfh);
    cudaGetSymbolAddress((void**)&qkvh, g_qkvh);
    cudaGetSymbolAddress((void**)&qkvl, g_qkvl);
    cudaGetSymbolAddress((void**)&Ath, g_Ath);
    cudaGetSymbolAddress((void**)&Atl, g_Atl);

    cudaFuncSetAttribute(gemm_f16x2,
                         cudaFuncAttributeMaxDynamicSharedMemorySize, GEMM_SMEM_BYTES);
    cudaFuncSetAttribute(attn_f16x2,
                         cudaFuncAttributeMaxDynamicSharedMemorySize, ATTN_SMEM_BYTES);

    // 0) conversions
    {
        const int n4 = MTOK * E_ / 4;
        convert_split16<<<(n4 + 255) / 256, 256>>>(
            (const float4*)X, (uint32_t*)Xh, (uint32_t*)Xl, n4);
        wt_convert16<<<dim3(QKV_N / 32, KDIM / 32), 256>>>(Wqkv, Wqh, KDIM, QKV_N);
        wt_convert16<<<dim3(HD_ / 32, KDIM / 32), 256>>>(Wfc, Wfh, KDIM, HD_);
    }

    // 1) QKV = X @ Wqkv + b -> fp16 hi/lo
    gemm_f16x2<<<dim3(QKV_N / 128, MTOK / 128), 256, GEMM_SMEM_BYTES>>>(
        Xh, Xl, Wqh, bqkv, nullptr, qkvh, qkvl, QKV_N);

    // 2) attention -> fp16 hi/lo
    attn_f16x2<<<dim3(L_ / 128, H_, B_), 256, ATTN_SMEM_BYTES>>>(
        qkvh, qkvl, Ath, Atl);

    // 3) FC -> fp32 out
    gemm_f16x2<<<dim3(HD_ / 128, MTOK / 128), 256, GEMM_SMEM_BYTES>>>(
        Ath, Atl, Wfh, bfc, out, nullptr, nullptr, HD_);
}